// round 11
// baseline (speedup 1.0000x reference)
#include <cuda_runtime.h>
#include <cuda_fp16.h>
#include <math.h>
#include <stdint.h>

#define NTOK 4096
#define DM   256
#define HD   64
#define KSTR 72    // attention smem stride (halves): 64 + 8 pad
#define GSTR 72    // gemm W smem stride (halves)
#define ASTR 264   // gemm A smem stride (halves): 256 + 8 pad

// ---------------- scratch ----------------------------------------------------
__device__ __half g_qh[NTOK * DM], g_kh[NTOK * DM], g_vh[NTOK * DM];
__device__ __half g_WQ[DM * DM], g_WK[DM * DM], g_WV[DM * DM], g_WO[DM * DM];
__device__ __half g_Qh[NTOK * DM];   // projected Q (scaled by 0.125*log2e)
__device__ __half g_Kh[NTOK * DM];
__device__ __half g_Vh[NTOK * DM];
__device__ __half g_Oh[NTOK * DM];
__device__ float  g_cos[NTOK * 32];
__device__ float  g_sin[NTOK * 32];

// ---------------- helpers ----------------------------------------------------
__device__ __forceinline__ uint32_t smem_u32(const void* p) {
    uint32_t a;
    asm("{ .reg .u64 t; cvta.to.shared.u64 t, %1; cvt.u32.u64 %0, t; }" : "=r"(a) : "l"(p));
    return a;
}
__device__ __forceinline__ void cp16(uint32_t dst, const void* src) {
    asm volatile("cp.async.ca.shared.global [%0], [%1], 16;" :: "r"(dst), "l"(src));
}
#define CP_COMMIT() asm volatile("cp.async.commit_group;" ::: "memory")
#define CP_WAIT(n)  asm volatile("cp.async.wait_group %0;" :: "n"(n) : "memory")

__device__ __forceinline__ void ldsm4(uint32_t a, uint32_t& r0, uint32_t& r1,
                                      uint32_t& r2, uint32_t& r3) {
    asm volatile("ldmatrix.sync.aligned.m8n8.x4.shared.b16 {%0,%1,%2,%3}, [%4];"
                 : "=r"(r0), "=r"(r1), "=r"(r2), "=r"(r3) : "r"(a));
}
__device__ __forceinline__ void ldsm4t(uint32_t a, uint32_t& r0, uint32_t& r1,
                                       uint32_t& r2, uint32_t& r3) {
    asm volatile("ldmatrix.sync.aligned.m8n8.x4.trans.shared.b16 {%0,%1,%2,%3}, [%4];"
                 : "=r"(r0), "=r"(r1), "=r"(r2), "=r"(r3) : "r"(a));
}
__device__ __forceinline__ void mma16816(float* c, uint32_t a0, uint32_t a1,
                                         uint32_t a2, uint32_t a3,
                                         uint32_t b0, uint32_t b1) {
    asm volatile(
        "mma.sync.aligned.m16n8k16.row.col.f32.f16.f16.f32 "
        "{%0,%1,%2,%3},{%4,%5,%6,%7},{%8,%9},{%0,%1,%2,%3};"
        : "+f"(c[0]), "+f"(c[1]), "+f"(c[2]), "+f"(c[3])
        : "r"(a0), "r"(a1), "r"(a2), "r"(a3), "r"(b0), "r"(b1));
}
__device__ __forceinline__ uint32_t pack2(float lo, float hi) {
    __half2 h = __floats2half2_rn(lo, hi);
    return *(uint32_t*)&h;
}

// ---------------- prep: cvt fp32->fp16 (inputs+weights) + rope table ---------
__global__ void prep_kernel(const float* q, const float* k, const float* v,
                            const float* wq, const float* wk,
                            const float* wv, const float* wo) {
    const int NM4 = NTOK * DM / 4;       // 262144
    const int W4  = DM * DM / 4;         // 16384
    const int CVT = 3 * NM4 + 4 * W4;    // 851968
    int i = blockIdx.x * blockDim.x + threadIdx.x;
    if (i < CVT) {
        const float* src;
        __half* dst;
        int off;
        if (i < 3 * NM4) {
            int t = i / NM4; off = i - t * NM4;
            src = (t == 0) ? q : (t == 1) ? k : v;
            dst = (t == 0) ? g_qh : (t == 1) ? g_kh : g_vh;
        } else {
            int j = i - 3 * NM4;
            int t = j / W4; off = j - t * W4;
            src = (t == 0) ? wq : (t == 1) ? wk : (t == 2) ? wv : wo;
            dst = (t == 0) ? g_WQ : (t == 1) ? g_WK : (t == 2) ? g_WV : g_WO;
        }
        float4 f = ((const float4*)src)[off];
        uint2 h;
        h.x = pack2(f.x, f.y);
        h.y = pack2(f.z, f.w);
        ((uint2*)dst)[off] = h;
    } else {
        int idx = i - CVT;
        if (idx >= NTOK * 32) return;
        int n = idx >> 5;
        int j = idx & 31;
        float pos = (j < 16) ? (float)(n & 63) : (float)(n >> 6);
        int jj = j & 15;
        float f = expf(-(float)jj * (9.210340371976184f / 16.0f));
        float s, c;
        sincosf(pos * f, &s, &c);
        g_cos[idx] = c;
        g_sin[idx] = s;
    }
}

// ---------------- fp16 tensor GEMM: full-K single-load, no k-pipeline --------
// BM=128 BN=64, K=256 entirely in smem. 256 threads (8 warps x m16).
// smem: A 128 x ASTR halves @0 (67584B) | W 256 x GSTR halves @67584 (36864B)
#define GEMM_SMEM 104448
__device__ __forceinline__ void gemm16_body(
    const __half* __restrict__ A, const __half* __restrict__ W,
    const float* __restrict__ bias, float* __restrict__ Cf,
    __half* __restrict__ Ch, int applyRope, float outScale) {
    extern __shared__ __align__(16) char gsm[];
    const uint32_t asm0 = smem_u32(gsm);
    const uint32_t wsm0 = asm0 + 67584;
    const int tid = threadIdx.x, wid = tid >> 5, L = tid & 31;
    const int bm = blockIdx.x * 128, bn = blockIdx.y * 64;

    // ---- one-shot loads: A 128x256 (4096 chunks), W 256x64 (2048 chunks) ----
    #pragma unroll
    for (int t = 0; t < 16; t++) {
        int it = tid + t * 256;
        int row = it >> 5, ch = it & 31;
        cp16(asm0 + (row * ASTR + ch * 8) * 2, &A[(bm + row) * DM + ch * 8]);
    }
    #pragma unroll
    for (int t = 0; t < 8; t++) {
        int it = tid + t * 256;
        int row = it >> 3, ch = it & 7;
        cp16(wsm0 + (row * GSTR + ch * 8) * 2, &W[row * DM + bn + ch * 8]);
    }
    CP_COMMIT();
    CP_WAIT(0);
    __syncthreads();

    const uint32_t qaddr = asm0 + ((wid * 16 + (L & 15)) * ASTR + (L >> 4) * 8) * 2;
    const int brow = ((L >> 3) & 1) * 8 + (L & 7);
    const int bcol = (L >> 4) * 8;
    float acc[8][4] = {};

    #pragma unroll
    for (int ks = 0; ks < 16; ks++) {
        uint32_t a0, a1, a2, a3;
        ldsm4(qaddr + ks * 32, a0, a1, a2, a3);
        #pragma unroll
        for (int np = 0; np < 4; np++) {
            uint32_t b0, b1, b2, b3;
            ldsm4t(wsm0 + ((ks * 16 + brow) * GSTR + np * 16 + bcol) * 2, b0, b1, b2, b3);
            mma16816(acc[np * 2], a0, a1, a2, a3, b0, b1);
            mma16816(acc[np * 2 + 1], a0, a1, a2, a3, b2, b3);
        }
    }

    const int r0 = bm + wid * 16 + (L >> 2);
    const int r1 = r0 + 8;
    #pragma unroll
    for (int j = 0; j < 8; j++) {
        const int col = bn + j * 8 + (L & 3) * 2;
        float v0 = acc[j][0] + bias[col], v1 = acc[j][1] + bias[col + 1];
        float v2 = acc[j][2] + bias[col], v3 = acc[j][3] + bias[col + 1];
        if (applyRope) {
            int j0 = (col & 63) >> 1;
            float c0 = g_cos[r0 * 32 + j0], s0 = g_sin[r0 * 32 + j0];
            float c1 = g_cos[r1 * 32 + j0], s1 = g_sin[r1 * 32 + j0];
            float t0 = v0 * c0 - v1 * s0, t1 = v0 * s0 + v1 * c0;
            float t2 = v2 * c1 - v3 * s1, t3 = v2 * s1 + v3 * c1;
            v0 = t0; v1 = t1; v2 = t2; v3 = t3;
        }
        if (Ch) {
            *(uint32_t*)&Ch[r0 * DM + col] = pack2(v0 * outScale, v1 * outScale);
            *(uint32_t*)&Ch[r1 * DM + col] = pack2(v2 * outScale, v3 * outScale);
        } else {
            *(float2*)&Cf[r0 * DM + col] = make_float2(v0, v1);
            *(float2*)&Cf[r1 * DM + col] = make_float2(v2, v3);
        }
    }
}

// merged QKV projection: grid (32, 4, 3)
__global__ void __launch_bounds__(256)
gemm_qkv_kernel(const float* __restrict__ bq, const float* __restrict__ bk,
                const float* __restrict__ bv) {
    const int z = blockIdx.z;
    const __half* A = (z == 0) ? g_qh : (z == 1) ? g_kh : g_vh;
    const __half* W = (z == 0) ? g_WQ : (z == 1) ? g_WK : g_WV;
    const float* bias = (z == 0) ? bq : (z == 1) ? bk : bv;
    __half* C = (z == 0) ? g_Qh : (z == 1) ? g_Kh : g_Vh;
    const float sc = (z == 0) ? 0.18033688011112042f : 1.0f;  // 0.125*log2(e)
    gemm16_body(A, W, bias, nullptr, C, z < 2, sc);
}

__global__ void __launch_bounds__(256)
gemm_out_kernel(const float* __restrict__ bo, float* __restrict__ out) {
    gemm16_body(g_Oh, g_WO, bo, out, nullptr, 0, 1.0f);
}

// ---------------- fp16 flash attention: BM=64, 8 warps, key-split ------------
// grid (64 q-tiles, 4 heads), 256 threads. Warp w: mw=w&3 (16 q-rows),
// g=w>>2 (key half: keys [g*32, g*32+32) of each 64-key tile).
// Partial O/l combined in epilogue via smem. Static smem blob 46080B:
//   Q @0 (9216) | K0 @9216 | K1 @18432 | V0 @27648 | V1 @36864
//   epilogue combine buffer reuses @0..18432.
__global__ void __launch_bounds__(256)
attn_kernel() {
    __shared__ __align__(16) char blob[46080];
    const uint32_t base = smem_u32(blob);
    const uint32_t qb = base;
    const uint32_t kB[2] = {base + 9216, base + 18432};
    const uint32_t vB[2] = {base + 27648, base + 36864};

    const int tid = threadIdx.x;
    const int wid = tid >> 5;
    const int L = tid & 31;
    const int mw = wid & 3;
    const int g = wid >> 2;
    const int h = blockIdx.y;
    const int q0 = blockIdx.x * 64;
    const int cb = h * HD;
    const int m0 = mw * 16;

    // ---- prologue: Q tile (64x64 = 512 chunks), then K0/V0 ----
    #pragma unroll
    for (int t = 0; t < 2; t++) {
        int it = tid + t * 256;
        int row = it >> 3, ch = it & 7;
        cp16(qb + (row * KSTR + ch * 8) * 2, &g_Qh[(q0 + row) * DM + cb + ch * 8]);
    }
    CP_COMMIT();
    #pragma unroll
    for (int t = 0; t < 2; t++) {
        int it = tid + t * 256;
        int row = it >> 3, ch = it & 7;
        cp16(kB[0] + (row * KSTR + ch * 8) * 2, &g_Kh[row * DM + cb + ch * 8]);
    }
    #pragma unroll
    for (int t = 0; t < 2; t++) {
        int it = tid + t * 256;
        int row = it >> 3, ch = it & 7;
        cp16(vB[0] + (row * KSTR + ch * 8) * 2, &g_Vh[row * DM + cb + ch * 8]);
    }
    CP_COMMIT();

    const uint32_t qaddr = qb + ((m0 + (L & 15)) * KSTR + (L >> 4) * 8) * 2;
    const int krow = (L >> 4) * 8 + (L & 7);
    const int kcol = ((L >> 3) & 1) * 8;
    const int vrow = ((L >> 3) & 1) * 8 + (L & 7);
    const int vcol = (L >> 4) * 8;
    const uint32_t onesB = (L < 4) ? 0x3C003C00u : 0u;  // ones in col 0

    float oa[8][4] = {};
    float lacc[4] = {};

    for (int i = 0; i < 64; i++) {
        const int buf = i & 1;
        if (i + 1 < 64) {
            const int nb = (i + 1) & 1;
            const int kt = (i + 1) * 64;
            #pragma unroll
            for (int t = 0; t < 2; t++) {
                int it = tid + t * 256;
                int row = it >> 3, ch = it & 7;
                cp16(kB[nb] + (row * KSTR + ch * 8) * 2, &g_Kh[(kt + row) * DM + cb + ch * 8]);
            }
            #pragma unroll
            for (int t = 0; t < 2; t++) {
                int it = tid + t * 256;
                int row = it >> 3, ch = it & 7;
                cp16(vB[nb] + (row * KSTR + ch * 8) * 2, &g_Vh[(kt + row) * DM + cb + ch * 8]);
            }
            CP_COMMIT();
            CP_WAIT(1);
        } else {
            CP_WAIT(0);
        }
        __syncthreads();

        const uint32_t kb = kB[buf];
        const uint32_t vb = vB[buf];

        // ---- S' = (Q*log2e/8) @ K^T : this warp's 16 rows x 32 keys ----
        float sc[4][4] = {};
        #pragma unroll
        for (int kc4 = 0; kc4 < 4; kc4++) {
            const int kc = kc4 * 16;
            uint32_t a0, a1, a2, a3;
            ldsm4(qaddr + kc * 2, a0, a1, a2, a3);
            #pragma unroll
            for (int np = 0; np < 2; np++) {
                const int n0 = g * 32 + np * 16;
                uint32_t b0, b1, b2, b3;
                ldsm4(kb + ((n0 + krow) * KSTR + kc + kcol) * 2, b0, b1, b2, b3);
                mma16816(sc[np * 2], a0, a1, a2, a3, b0, b1);
                mma16816(sc[np * 2 + 1], a0, a1, a2, a3, b2, b3);
            }
        }

        // ---- P = 2^(S') packed f16x2 ----
        uint32_t pf[4][2];
        #pragma unroll
        for (int j = 0; j < 4; j++) {
            __half2 e0 = h2exp2(__floats2half2_rn(sc[j][0], sc[j][1]));
            __half2 e1 = h2exp2(__floats2half2_rn(sc[j][2], sc[j][3]));
            pf[j][0] = *(uint32_t*)&e0;
            pf[j][1] = *(uint32_t*)&e1;
        }

        // ---- O_partial += P @ V (this warp's 32 keys) ; l_partial += P@ones --
        #pragma unroll
        for (int c = 0; c < 2; c++) {
            const int kc = g * 32 + c * 16;
            const uint32_t a0 = pf[2 * c][0], a1 = pf[2 * c][1];
            const uint32_t a2 = pf[2 * c + 1][0], a3 = pf[2 * c + 1][1];
            #pragma unroll
            for (int dp = 0; dp < 4; dp++) {
                const int n0 = dp * 16;
                uint32_t b0, b1, b2, b3;
                ldsm4t(vb + ((kc + vrow) * KSTR + n0 + vcol) * 2, b0, b1, b2, b3);
                mma16816(oa[dp * 2], a0, a1, a2, a3, b0, b1);
                mma16816(oa[dp * 2 + 1], a0, a1, a2, a3, b2, b3);
            }
            mma16816(lacc, a0, a1, a2, a3, onesB, onesB);
        }
        __syncthreads();
    }

    // ---- combine partials across key groups, normalize, store ----
    float* cbuf = (float*)blob;               // reuse smem (all K/V reads done)
    const int slot = (mw * 32 + L) * 36;      // 32 oa + 4 lacc floats per lane
    if (g == 1) {
        #pragma unroll
        for (int j = 0; j < 8; j++)
            *(float4*)&cbuf[slot + j * 4] =
                make_float4(oa[j][0], oa[j][1], oa[j][2], oa[j][3]);
        *(float4*)&cbuf[slot + 32] = make_float4(lacc[0], lacc[1], lacc[2], lacc[3]);
    }
    __syncthreads();
    if (g == 0) {
        #pragma unroll
        for (int j = 0; j < 8; j++) {
            float4 o2 = *(float4*)&cbuf[slot + j * 4];
            oa[j][0] += o2.x; oa[j][1] += o2.y; oa[j][2] += o2.z; oa[j][3] += o2.w;
        }
        float4 l2 = *(float4*)&cbuf[slot + 32];
        lacc[0] += l2.x; lacc[2] += l2.z;

        const float l0 = __shfl_sync(0xffffffffu, lacc[0], L & 28);
        const float l1 = __shfl_sync(0xffffffffu, lacc[2], L & 28);
        const float inv0 = 1.0f / l0;
        const float inv1 = 1.0f / l1;
        const int r0 = q0 + m0 + (L >> 2);
        const int cc = (L & 3) * 2;
        #pragma unroll
        for (int j = 0; j < 8; j++) {
            *(uint32_t*)&g_Oh[r0 * DM + cb + j * 8 + cc] =
                pack2(oa[j][0] * inv0, oa[j][1] * inv0);
            *(uint32_t*)&g_Oh[(r0 + 8) * DM + cb + j * 8 + cc] =
                pack2(oa[j][2] * inv1, oa[j][3] * inv1);
        }
    }
}

// ---------------- launch -----------------------------------------------------
extern "C" void kernel_launch(void* const* d_in, const int* in_sizes, int n_in,
                              void* d_out, int out_size) {
    const float* q  = (const float*)d_in[0];
    const float* k  = (const float*)d_in[1];
    const float* v  = (const float*)d_in[2];
    const float* wq = (const float*)d_in[3];
    const float* bq = (const float*)d_in[4];
    const float* wk = (const float*)d_in[5];
    const float* bk = (const float*)d_in[6];
    const float* wv = (const float*)d_in[7];
    const float* bv = (const float*)d_in[8];
    const float* wo = (const float*)d_in[9];
    const float* bo = (const float*)d_in[10];
    float* out = (float*)d_out;

    cudaFuncSetAttribute(gemm_qkv_kernel, cudaFuncAttributeMaxDynamicSharedMemorySize, GEMM_SMEM);
    cudaFuncSetAttribute(gemm_out_kernel, cudaFuncAttributeMaxDynamicSharedMemorySize, GEMM_SMEM);

    const int prepTot = 3 * (NTOK * DM / 4) + 4 * (DM * DM / 4) + NTOK * 32;
    prep_kernel<<<(prepTot + 255) / 256, 256>>>(q, k, v, wq, wk, wv, wo);

    gemm_qkv_kernel<<<dim3(NTOK / 128, DM / 64, 3), 256, GEMM_SMEM>>>(bq, bk, bv);

    attn_kernel<<<dim3(NTOK / 64, 4), 256>>>();

    gemm_out_kernel<<<dim3(NTOK / 128, DM / 64), 256, GEMM_SMEM>>>(bo, out);
}

// round 14
// speedup vs baseline: 1.1292x; 1.1292x over previous
#include <cuda_runtime.h>
#include <cuda_fp16.h>
#include <math.h>
#include <stdint.h>

#define NTOK 4096
#define DM   256
#define HD   64
#define KSTR 72   // fp16 smem stride (halves): 64 + 8 pad
#define GSTR 72

// ---------------- scratch ----------------------------------------------------
__device__ __half g_qh[NTOK * DM], g_kh[NTOK * DM], g_vh[NTOK * DM];
__device__ __half g_WQ[DM * DM], g_WK[DM * DM], g_WV[DM * DM], g_WO[DM * DM];
__device__ __half g_Qh[NTOK * DM];   // projected Q (scaled by 0.125*log2e)
__device__ __half g_Kh[NTOK * DM];
__device__ __half g_Vh[NTOK * DM];
__device__ __half g_Oh[NTOK * DM];   // combined attention output (fp16)
__device__ float  g_Op[2][NTOK * DM];  // split-K partial O (unnormalized, fp32)
__device__ float  g_L[2][4 * NTOK];    // split-K partial row sums, [s][h*NTOK+row]
__device__ float  g_cos[NTOK * 32];
__device__ float  g_sin[NTOK * 32];

// ---------------- helpers ----------------------------------------------------
__device__ __forceinline__ uint32_t smem_u32(const void* p) {
    uint32_t a;
    asm("{ .reg .u64 t; cvta.to.shared.u64 t, %1; cvt.u32.u64 %0, t; }" : "=r"(a) : "l"(p));
    return a;
}
__device__ __forceinline__ void cp16(uint32_t dst, const void* src) {
    asm volatile("cp.async.ca.shared.global [%0], [%1], 16;" :: "r"(dst), "l"(src));
}
#define CP_COMMIT() asm volatile("cp.async.commit_group;" ::: "memory")
#define CP_WAIT(n)  asm volatile("cp.async.wait_group %0;" :: "n"(n) : "memory")

__device__ __forceinline__ void ldsm4(uint32_t a, uint32_t& r0, uint32_t& r1,
                                      uint32_t& r2, uint32_t& r3) {
    asm volatile("ldmatrix.sync.aligned.m8n8.x4.shared.b16 {%0,%1,%2,%3}, [%4];"
                 : "=r"(r0), "=r"(r1), "=r"(r2), "=r"(r3) : "r"(a));
}
__device__ __forceinline__ void ldsm4t(uint32_t a, uint32_t& r0, uint32_t& r1,
                                       uint32_t& r2, uint32_t& r3) {
    asm volatile("ldmatrix.sync.aligned.m8n8.x4.trans.shared.b16 {%0,%1,%2,%3}, [%4];"
                 : "=r"(r0), "=r"(r1), "=r"(r2), "=r"(r3) : "r"(a));
}
__device__ __forceinline__ void mma16816(float* c, uint32_t a0, uint32_t a1,
                                         uint32_t a2, uint32_t a3,
                                         uint32_t b0, uint32_t b1) {
    asm volatile(
        "mma.sync.aligned.m16n8k16.row.col.f32.f16.f16.f32 "
        "{%0,%1,%2,%3},{%4,%5,%6,%7},{%8,%9},{%0,%1,%2,%3};"
        : "+f"(c[0]), "+f"(c[1]), "+f"(c[2]), "+f"(c[3])
        : "r"(a0), "r"(a1), "r"(a2), "r"(a3), "r"(b0), "r"(b1));
}
__device__ __forceinline__ uint32_t pack2(float lo, float hi) {
    __half2 h = __floats2half2_rn(lo, hi);
    return *(uint32_t*)&h;
}

// ---------------- prep: cvt fp32->fp16 (inputs+weights) + rope table ---------
__global__ void prep_kernel(const float* q, const float* k, const float* v,
                            const float* wq, const float* wk,
                            const float* wv, const float* wo) {
    const int NM4 = NTOK * DM / 4;
    const int W4  = DM * DM / 4;
    const int CVT = 3 * NM4 + 4 * W4;
    int i = blockIdx.x * blockDim.x + threadIdx.x;
    if (i < CVT) {
        const float* src;
        __half* dst;
        int off;
        if (i < 3 * NM4) {
            int t = i / NM4; off = i - t * NM4;
            src = (t == 0) ? q : (t == 1) ? k : v;
            dst = (t == 0) ? g_qh : (t == 1) ? g_kh : g_vh;
        } else {
            int j = i - 3 * NM4;
            int t = j / W4; off = j - t * W4;
            src = (t == 0) ? wq : (t == 1) ? wk : (t == 2) ? wv : wo;
            dst = (t == 0) ? g_WQ : (t == 1) ? g_WK : (t == 2) ? g_WV : g_WO;
        }
        float4 f = ((const float4*)src)[off];
        uint2 h;
        h.x = pack2(f.x, f.y);
        h.y = pack2(f.z, f.w);
        ((uint2*)dst)[off] = h;
    } else {
        int idx = i - CVT;
        if (idx >= NTOK * 32) return;
        int n = idx >> 5;
        int j = idx & 31;
        float pos = (j < 16) ? (float)(n & 63) : (float)(n >> 6);
        int jj = j & 15;
        float f = expf(-(float)jj * (9.210340371976184f / 16.0f));
        float s, c;
        sincosf(pos * f, &s, &c);
        g_cos[idx] = c;
        g_sin[idx] = s;
    }
}

// ---------------- fp16 tensor GEMM body (R6 double-buffered version) ---------
#define GEMM_SMEM 57600
__device__ __forceinline__ void gemm16_body(
    const __half* __restrict__ A, const __half* __restrict__ W,
    const float* __restrict__ bias, float* __restrict__ Cf,
    __half* __restrict__ Ch, int applyRope, float outScale) {
    extern __shared__ __align__(16) char gsm[];
    const uint32_t base = smem_u32(gsm);
    const int tid = threadIdx.x, wid = tid >> 5, L = tid & 31;
    const int bm = blockIdx.x * 128, bn = blockIdx.y * 64;

    const uint32_t aBuf[2] = {base, base + 18432};
    const uint32_t wBuf[2] = {base + 36864, base + 47232};

    auto loadChunk = [&](int k0, int b) {
        #pragma unroll
        for (int t = 0; t < 4; t++) {
            int it = tid + t * 256;
            int row = it >> 3, ch = it & 7;
            cp16(aBuf[b] + (row * GSTR + ch * 8) * 2, &A[(bm + row) * DM + k0 + ch * 8]);
        }
        #pragma unroll
        for (int t = 0; t < 2; t++) {
            int it = tid + t * 256;
            int row = it >> 3, ch = it & 7;
            cp16(wBuf[b] + (row * GSTR + ch * 8) * 2, &W[(k0 + row) * DM + bn + ch * 8]);
        }
        CP_COMMIT();
    };

    loadChunk(0, 0);

    const int brow = ((L >> 3) & 1) * 8 + (L & 7);
    const int bcol = (L >> 4) * 8;
    float acc[8][4] = {};

    #pragma unroll
    for (int kk = 0; kk < 4; kk++) {
        CP_WAIT(0);
        __syncthreads();
        if (kk < 3) loadChunk((kk + 1) * 64, (kk + 1) & 1);
        const uint32_t aA = aBuf[kk & 1];
        const uint32_t aW = wBuf[kk & 1];
        const uint32_t qaddr = aA + ((wid * 16 + (L & 15)) * GSTR + (L >> 4) * 8) * 2;
        #pragma unroll
        for (int kc4 = 0; kc4 < 4; kc4++) {
            const int kc = kc4 * 16;
            uint32_t a0, a1, a2, a3;
            ldsm4(qaddr + kc * 2, a0, a1, a2, a3);
            #pragma unroll
            for (int np = 0; np < 4; np++) {
                const int n0 = np * 16;
                uint32_t b0, b1, b2, b3;
                ldsm4t(aW + ((kc + brow) * GSTR + n0 + bcol) * 2, b0, b1, b2, b3);
                mma16816(acc[np * 2], a0, a1, a2, a3, b0, b1);
                mma16816(acc[np * 2 + 1], a0, a1, a2, a3, b2, b3);
            }
        }
        __syncthreads();
    }

    const int r0 = bm + wid * 16 + (L >> 2);
    const int r1 = r0 + 8;
    #pragma unroll
    for (int j = 0; j < 8; j++) {
        const int col = bn + j * 8 + (L & 3) * 2;
        float v0 = acc[j][0] + bias[col], v1 = acc[j][1] + bias[col + 1];
        float v2 = acc[j][2] + bias[col], v3 = acc[j][3] + bias[col + 1];
        if (applyRope) {
            int j0 = (col & 63) >> 1;
            float c0 = g_cos[r0 * 32 + j0], s0 = g_sin[r0 * 32 + j0];
            float c1 = g_cos[r1 * 32 + j0], s1 = g_sin[r1 * 32 + j0];
            float t0 = v0 * c0 - v1 * s0, t1 = v0 * s0 + v1 * c0;
            float t2 = v2 * c1 - v3 * s1, t3 = v2 * s1 + v3 * c1;
            v0 = t0; v1 = t1; v2 = t2; v3 = t3;
        }
        if (Ch) {
            *(uint32_t*)&Ch[r0 * DM + col] = pack2(v0 * outScale, v1 * outScale);
            *(uint32_t*)&Ch[r1 * DM + col] = pack2(v2 * outScale, v3 * outScale);
        } else {
            *(float2*)&Cf[r0 * DM + col] = make_float2(v0, v1);
            *(float2*)&Cf[r1 * DM + col] = make_float2(v2, v3);
        }
    }
}

__global__ void __launch_bounds__(256)
gemm_qkv_kernel(const float* __restrict__ bq, const float* __restrict__ bk,
                const float* __restrict__ bv) {
    const int z = blockIdx.z;
    const __half* A = (z == 0) ? g_qh : (z == 1) ? g_kh : g_vh;
    const __half* W = (z == 0) ? g_WQ : (z == 1) ? g_WK : g_WV;
    const float* bias = (z == 0) ? bq : (z == 1) ? bk : bv;
    __half* C = (z == 0) ? g_Qh : (z == 1) ? g_Kh : g_Vh;
    const float sc = (z == 0) ? 0.18033688011112042f : 1.0f;  // 0.125*log2(e)
    gemm16_body(A, W, bias, nullptr, C, z < 2, sc);
}

__global__ void __launch_bounds__(256)
gemm_out_kernel(const float* __restrict__ bo, float* __restrict__ out) {
    gemm16_body(g_Oh, g_WO, bo, out, nullptr, 0, 1.0f);
}

// ---------------- fp16 flash attention: BM=64, 4 warps, split-K x2 -----------
// grid (64 q-tiles, 4 heads, 2 key-splits), 128 threads. Each CTA handles
// 2048 keys (32 tiles of 64). Partial O (fp32, unnormalized) + partial l
// written to globals; combine_kernel normalizes. Q frags hoisted out of loop.
__global__ void __launch_bounds__(128)
attn_kernel() {
    __shared__ __half sQ[64 * KSTR];
    __shared__ __half sK[2][64 * KSTR];
    __shared__ __half sV[2][64 * KSTR];

    const int tid = threadIdx.x;
    const int wid = tid >> 5;
    const int L = tid & 31;
    const int h = blockIdx.y;
    const int s = blockIdx.z;
    const int q0 = blockIdx.x * 64;
    const int kt0 = s * 2048;
    const int cb = h * HD;
    const int m0 = wid * 16;

    const uint32_t qb = smem_u32(sQ);
    const uint32_t kb0 = smem_u32(sK[0]);
    const uint32_t vb0 = smem_u32(sV[0]);
    const uint32_t tileB = 64 * KSTR * 2;

    {
        #pragma unroll
        for (int t = 0; t < 4; t++) {
            int it = tid + t * 128;
            int row = it >> 3, ch = it & 7;
            cp16(qb + (row * KSTR + ch * 8) * 2, &g_Qh[(q0 + row) * DM + cb + ch * 8]);
        }
        CP_COMMIT();
        #pragma unroll
        for (int t = 0; t < 4; t++) {
            int it = tid + t * 128;
            int row = it >> 3, ch = it & 7;
            cp16(kb0 + (row * KSTR + ch * 8) * 2, &g_Kh[(kt0 + row) * DM + cb + ch * 8]);
        }
        #pragma unroll
        for (int t = 0; t < 4; t++) {
            int it = tid + t * 128;
            int row = it >> 3, ch = it & 7;
            cp16(vb0 + (row * KSTR + ch * 8) * 2, &g_Vh[(kt0 + row) * DM + cb + ch * 8]);
        }
        CP_COMMIT();
    }

    const uint32_t qaddr = qb + ((m0 + (L & 15)) * KSTR + (L >> 4) * 8) * 2;
    const int krow = (L >> 4) * 8 + (L & 7);
    const int kcol = ((L >> 3) & 1) * 8;
    const int vrow = ((L >> 3) & 1) * 8 + (L & 7);
    const int vcol = (L >> 4) * 8;
    const uint32_t onesB = (L < 4) ? 0x3C003C00u : 0u;  // ones in col 0

    // ---- hoist loop-invariant Q fragments ----
    CP_WAIT(1);
    __syncthreads();
    uint32_t qf[4][4];
    #pragma unroll
    for (int kc4 = 0; kc4 < 4; kc4++)
        ldsm4(qaddr + kc4 * 32, qf[kc4][0], qf[kc4][1], qf[kc4][2], qf[kc4][3]);

    float oa[8][4] = {};
    float lacc[4] = {};

    for (int i = 0; i < 32; i++) {
        const int buf = i & 1;
        if (i + 1 < 32) {
            const int nb = (i + 1) & 1;
            const uint32_t kbn = kb0 + nb * tileB;
            const uint32_t vbn = vb0 + nb * tileB;
            const int kt = kt0 + (i + 1) * 64;
            #pragma unroll
            for (int t = 0; t < 4; t++) {
                int it = tid + t * 128;
                int row = it >> 3, ch = it & 7;
                cp16(kbn + (row * KSTR + ch * 8) * 2, &g_Kh[(kt + row) * DM + cb + ch * 8]);
            }
            #pragma unroll
            for (int t = 0; t < 4; t++) {
                int it = tid + t * 128;
                int row = it >> 3, ch = it & 7;
                cp16(vbn + (row * KSTR + ch * 8) * 2, &g_Vh[(kt + row) * DM + cb + ch * 8]);
            }
            CP_COMMIT();
            CP_WAIT(1);
        } else {
            CP_WAIT(0);
        }
        __syncthreads();

        const uint32_t kb = kb0 + buf * tileB;
        const uint32_t vb = vb0 + buf * tileB;

        // ---- S' = (Q*log2e/8) @ K^T ----
        float sc[8][4] = {};
        #pragma unroll
        for (int kc4 = 0; kc4 < 4; kc4++) {
            const int kc = kc4 * 16;
            #pragma unroll
            for (int np = 0; np < 4; np++) {
                const int n0 = np * 16;
                uint32_t b0, b1, b2, b3;
                ldsm4(kb + ((n0 + krow) * KSTR + kc + kcol) * 2, b0, b1, b2, b3);
                mma16816(sc[np * 2], qf[kc4][0], qf[kc4][1], qf[kc4][2], qf[kc4][3], b0, b1);
                mma16816(sc[np * 2 + 1], qf[kc4][0], qf[kc4][1], qf[kc4][2], qf[kc4][3], b2, b3);
            }
        }

        // ---- P = 2^(S') packed f16x2 ----
        uint32_t pf[8][2];
        #pragma unroll
        for (int j = 0; j < 8; j++) {
            __half2 e0 = h2exp2(__floats2half2_rn(sc[j][0], sc[j][1]));
            __half2 e1 = h2exp2(__floats2half2_rn(sc[j][2], sc[j][3]));
            pf[j][0] = *(uint32_t*)&e0;
            pf[j][1] = *(uint32_t*)&e1;
        }

        // ---- O += P @ V ; l += P @ ones ----
        #pragma unroll
        for (int c = 0; c < 4; c++) {
            const int kc = c * 16;
            const uint32_t a0 = pf[2 * c][0], a1 = pf[2 * c][1];
            const uint32_t a2 = pf[2 * c + 1][0], a3 = pf[2 * c + 1][1];
            #pragma unroll
            for (int dp = 0; dp < 4; dp++) {
                const int n0 = dp * 16;
                uint32_t b0, b1, b2, b3;
                ldsm4t(vb + ((kc + vrow) * KSTR + n0 + vcol) * 2, b0, b1, b2, b3);
                mma16816(oa[dp * 2], a0, a1, a2, a3, b0, b1);
                mma16816(oa[dp * 2 + 1], a0, a1, a2, a3, b2, b3);
            }
            mma16816(lacc, a0, a1, a2, a3, onesB, onesB);
        }
        __syncthreads();
    }

    // ---- store unnormalized partials ----
    const int r0 = q0 + m0 + (L >> 2);
    const int cc = (L & 3) * 2;
    float* op = g_Op[s];
    #pragma unroll
    for (int j = 0; j < 8; j++) {
        *(float2*)&op[r0 * DM + cb + j * 8 + cc] = make_float2(oa[j][0], oa[j][1]);
        *(float2*)&op[(r0 + 8) * DM + cb + j * 8 + cc] = make_float2(oa[j][2], oa[j][3]);
    }
    if ((L & 3) == 0) {
        g_L[s][h * NTOK + r0] = lacc[0];
        g_L[s][h * NTOK + r0 + 8] = lacc[2];
    }
}

// ---------------- combine split-K partials -> fp16 O -------------------------
__global__ void combine_kernel() {
    int i = blockIdx.x * blockDim.x + threadIdx.x;  // one float4 (4 cols)
    if (i >= NTOK * DM / 4) return;
    int row = i / (DM / 4);
    int col = (i % (DM / 4)) * 4;
    int h = col >> 6;
    float l = g_L[0][h * NTOK + row] + g_L[1][h * NTOK + row];
    float inv = 1.0f / l;
    float4 a = *(const float4*)&g_Op[0][row * DM + col];
    float4 b = *(const float4*)&g_Op[1][row * DM + col];
    uint2 o;
    o.x = pack2((a.x + b.x) * inv, (a.y + b.y) * inv);
    o.y = pack2((a.z + b.z) * inv, (a.w + b.w) * inv);
    *(uint2*)&g_Oh[row * DM + col] = o;
}

// ---------------- launch -----------------------------------------------------
extern "C" void kernel_launch(void* const* d_in, const int* in_sizes, int n_in,
                              void* d_out, int out_size) {
    const float* q  = (const float*)d_in[0];
    const float* k  = (const float*)d_in[1];
    const float* v  = (const float*)d_in[2];
    const float* wq = (const float*)d_in[3];
    const float* bq = (const float*)d_in[4];
    const float* wk = (const float*)d_in[5];
    const float* bk = (const float*)d_in[6];
    const float* wv = (const float*)d_in[7];
    const float* bv = (const float*)d_in[8];
    const float* wo = (const float*)d_in[9];
    const float* bo = (const float*)d_in[10];
    float* out = (float*)d_out;

    cudaFuncSetAttribute(gemm_qkv_kernel, cudaFuncAttributeMaxDynamicSharedMemorySize, GEMM_SMEM);
    cudaFuncSetAttribute(gemm_out_kernel, cudaFuncAttributeMaxDynamicSharedMemorySize, GEMM_SMEM);

    const int prepTot = 3 * (NTOK * DM / 4) + 4 * (DM * DM / 4) + NTOK * 32;
    prep_kernel<<<(prepTot + 255) / 256, 256>>>(q, k, v, wq, wk, wv, wo);

    gemm_qkv_kernel<<<dim3(NTOK / 128, DM / 64, 3), 256, GEMM_SMEM>>>(bq, bk, bv);

    attn_kernel<<<dim3(NTOK / 64, 4, 2), 128>>>();
    combine_kernel<<<(NTOK * DM / 4 + 255) / 256, 256>>>();

    gemm_out_kernel<<<dim3(NTOK / 128, DM / 64), 256, GEMM_SMEM>>>(bo, out);
}